// round 13
// baseline (speedup 1.0000x reference)
#include <cuda_runtime.h>
#include <cuda_fp16.h>
#include <cstdint>

#define B_    16
#define L_    256
#define D_    512
#define MELS_ 80
#define T_    3072
#define M_ENC (B_ * L_)   // 4096
#define NCTA  256

// Scratch (__device__ globals; no allocation allowed)
__device__ __half g_x    [M_ENC * D_];
__device__ __half g_enc  [M_ENC * D_];
__device__ __half g_dect [M_ENC * D_];
__device__ int    g_csum [B_ * L_];
__device__ float  g_melP [8 * MELS_ * M_ENC];  // per-bx gen partials [bx][n][tok]
__device__ float  g_melT [MELS_ * M_ENC];      // reduced melT[n][tok] (with bias)
__device__ float  g_cmel [MELS_];              // mel column for invalid frames (with bias)
__device__ __half g_wencT[D_ * D_];
__device__ __half g_wdecT[D_ * D_];
__device__ __half g_wgenT[MELS_ * D_];         // [n][k] fp16, 1KB rows

__device__ unsigned g_bar;
__device__ int fWe[8], fWd[8], fWg, fC;
__device__ int fX[32], fE[32], fRB[32], fR[32], fS[16];

// ---------------------------------------------------------------------------
__device__ __forceinline__ uint32_t smem_u32(const void* p) {
    return (uint32_t)__cvta_generic_to_shared(p);
}
__device__ __forceinline__ void cpa16(uint32_t dst, const void* src, int srcsize) {
    asm volatile("cp.async.cg.shared.global [%0], [%1], 16, %2;"
                 :: "r"(dst), "l"(src), "r"(srcsize));
}
__device__ __forceinline__ uint32_t sw(uint32_t o) { return o ^ ((o >> 3) & 0x70); }

__device__ __forceinline__ void ldm4(uint32_t* r, uint32_t addr) {
    asm volatile("ldmatrix.sync.aligned.m8n8.x4.shared.b16 {%0,%1,%2,%3}, [%4];"
                 : "=r"(r[0]), "=r"(r[1]), "=r"(r[2]), "=r"(r[3]) : "r"(addr));
}
__device__ __forceinline__ void ldm2(uint32_t* r, uint32_t addr) {
    asm volatile("ldmatrix.sync.aligned.m8n8.x2.shared.b16 {%0,%1}, [%2];"
                 : "=r"(r[0]), "=r"(r[1]) : "r"(addr));
}
__device__ __forceinline__ void mma_f16(float* d, const uint32_t* a, const uint32_t* b) {
    asm volatile(
        "mma.sync.aligned.m16n8k16.row.col.f32.f16.f16.f32 "
        "{%0,%1,%2,%3},{%4,%5,%6,%7},{%8,%9},{%0,%1,%2,%3};"
        : "+f"(d[0]), "+f"(d[1]), "+f"(d[2]), "+f"(d[3])
        : "r"(a[0]), "r"(a[1]), "r"(a[2]), "r"(a[3]), "r"(b[0]), "r"(b[1]));
}

// release-signal / acquire-wait on global int flags
__device__ __forceinline__ void signal(int* f) {
    __threadfence();
    __syncthreads();
    if (threadIdx.x == 0) atomicAdd(f, 1);
}
__device__ __forceinline__ void waitf(int* f, int tgt) {
    if (threadIdx.x == 0) {
        while (*(volatile int*)f < tgt) __nanosleep(32);
        __threadfence();
    }
    __syncthreads();
}

// ---------------------------------------------------------------------------
// 32x32 transpose tile of a 512x512 fp32 weight -> fp16 [N][K]
__device__ void t_unit(const float* __restrict__ srcw, __half* __restrict__ dst,
                       int id, float* sbuf)
{
    const int tid = threadIdx.x;
    const int c0 = (id & 15) * 32, r0 = (id >> 4) * 32;
    const int tx = tid & 31, ty = tid >> 5;
    float (*tile)[33] = (float(*)[33])sbuf;
#pragma unroll
    for (int i = 0; i < 4; i++)
        tile[ty + i * 8][tx] = srcw[(r0 + ty + i * 8) * D_ + c0 + tx];
    __syncthreads();
#pragma unroll
    for (int i = 0; i < 4; i++)
        dst[(long)(c0 + ty + i * 8) * D_ + r0 + tx] =
            __float2half_rn(tile[tx][ty + i * 8]);
}

// ---------------------------------------------------------------------------
// enc GEMM tile 128m x 64n: out = fp16(relu(A @ Bt^T + bias))
// ---------------------------------------------------------------------------
#define A_T 16384
#define B_T 8192
#define STG (A_T + B_T)                 // 24576
#define SMEM_DYN (2 * STG + 1024)       // 50176

__device__ void dev_hgemm(const __half* __restrict__ A, const __half* __restrict__ Bt,
                          const float* __restrict__ bias, __half* __restrict__ out,
                          int bx, int by, char* dsm)
{
    const int tid  = threadIdx.x;
    const int warp = tid >> 5, lane = tid & 31;
    const int m0   = by * 128, n0 = bx * 64;

    const uint32_t base = (smem_u32(dsm) + 1023) & ~1023u;
    const uint32_t Aoff[2] = { base, base + STG };
    const uint32_t Boff[2] = { base + A_T, base + STG + A_T };

    const int r0  = tid >> 3;
    const int seg = (tid & 7) * 16;
    const char* ap[4];
    const char* bp[2];
    uint32_t dsta[4], dstb[2];
#pragma unroll
    for (int i = 0; i < 4; i++) {
        const int r = r0 + i * 32;
        ap[i]   = (const char*)A + (long)(m0 + r) * D_ * 2;
        dsta[i] = sw((uint32_t)(r * 128 + seg));
    }
#pragma unroll
    for (int i = 0; i < 2; i++) {
        const int r = r0 + i * 32;
        bp[i]   = (const char*)Bt + (long)(n0 + r) * D_ * 2;
        dstb[i] = sw((uint32_t)(r * 128 + seg));
    }

#define HISSUE(c, s) do {                                                     \
        const int kb = (c) * 128;                                             \
        _Pragma("unroll")                                                     \
        for (int i = 0; i < 4; i++) cpa16(Aoff[s] + dsta[i], ap[i] + kb + seg, 16); \
        _Pragma("unroll")                                                     \
        for (int i = 0; i < 2; i++) cpa16(Boff[s] + dstb[i], bp[i] + kb + seg, 16); \
        asm volatile("cp.async.commit_group;");                               \
    } while (0)

    const int mbase = (warp & 1) * 64;
    const int nbase = (warp >> 1) * 16;
    const int li  = lane & 7, grp = lane >> 3;
    const int ar  = (grp & 1) * 8 + li,  ak = (grp >> 1) * 16;
    const int br  = (grp >> 1) * 8 + li, bk = (grp & 1) * 16;
    const int g = lane >> 2, t = lane & 3;

    float acc[4][2][4] = {};

    HISSUE(0, 0);
#pragma unroll 1
    for (int c = 0; c < 8; c++) {
        if (c < 7) {
            HISSUE(c + 1, (c + 1) & 1);
            asm volatile("cp.async.wait_group 1;");
        } else {
            asm volatile("cp.async.wait_group 0;");
        }
        __syncthreads();
        const uint32_t Ab = Aoff[c & 1], Bb = Boff[c & 1];
#pragma unroll
        for (int kk = 0; kk < 4; kk++) {
            const int kb2 = kk * 32;
            uint32_t a[4][4], b[2][2];
#pragma unroll
            for (int mf = 0; mf < 4; mf++) {
                uint32_t o = (uint32_t)((mbase + mf * 16 + ar) * 128 + kb2 + ak);
                ldm4(a[mf], Ab + sw(o));
            }
            {
                uint32_t o = (uint32_t)((nbase + br) * 128 + kb2 + bk);
                uint32_t r[4]; ldm4(r, Bb + sw(o));
                b[0][0] = r[0]; b[0][1] = r[1];
                b[1][0] = r[2]; b[1][1] = r[3];
            }
#pragma unroll
            for (int mf = 0; mf < 4; mf++)
#pragma unroll
                for (int nf = 0; nf < 2; nf++)
                    mma_f16(acc[mf][nf], a[mf], b[nf]);
        }
        __syncthreads();
    }

#pragma unroll
    for (int mf = 0; mf < 4; mf++) {
        const long r0g = m0 + mbase + mf * 16 + g;
#pragma unroll
        for (int nf = 0; nf < 2; nf++) {
            const int c = n0 + nbase + nf * 8 + t * 2;
            const float b0 = bias[c], b1 = bias[c + 1];
            float v0 = acc[mf][nf][0] + b0, v1 = acc[mf][nf][1] + b1;
            float v2 = acc[mf][nf][2] + b0, v3 = acc[mf][nf][3] + b1;
            __half2 h0 = __floats2half2_rn(v0 > 0.f ? v0 : 0.f, v1 > 0.f ? v1 : 0.f);
            __half2 h1 = __floats2half2_rn(v2 > 0.f ? v2 : 0.f, v3 > 0.f ? v3 : 0.f);
            *(__half2*)(out + r0g * D_ + c)       = h0;
            *(__half2*)(out + (r0g + 8) * D_ + c) = h1;
        }
    }
#undef HISSUE
}

// ---------------------------------------------------------------------------
// dec GEMM tile + fused gen partial (as R11)
// ---------------------------------------------------------------------------
__device__ void dev_decgen(const float* __restrict__ bias, int bx, int by, char* dsm)
{
    const int tid  = threadIdx.x;
    const int warp = tid >> 5, lane = tid & 31;
    const int m0   = by * 128, n0 = bx * 64;

    char* p_al = (char*)(((uintptr_t)dsm + 1023) & ~(uintptr_t)1023);
    const uint32_t base = smem_u32(p_al);
    const uint32_t Aoff[2] = { base, base + STG };
    const uint32_t Boff[2] = { base + A_T, base + STG + A_T };

    const int r0  = tid >> 3;
    const int seg = (tid & 7) * 16;
    const char* ap[4];
    const char* bp[2];
    uint32_t dsta[4], dstb[2];
#pragma unroll
    for (int i = 0; i < 4; i++) {
        const int r = r0 + i * 32;
        ap[i]   = (const char*)g_enc + (long)(m0 + r) * D_ * 2;
        dsta[i] = sw((uint32_t)(r * 128 + seg));
    }
#pragma unroll
    for (int i = 0; i < 2; i++) {
        const int r = r0 + i * 32;
        bp[i]   = (const char*)g_wdecT + (long)(n0 + r) * D_ * 2;
        dstb[i] = sw((uint32_t)(r * 128 + seg));
    }

#define DISSUE(c, s) do {                                                     \
        const int kb = (c) * 128;                                             \
        _Pragma("unroll")                                                     \
        for (int i = 0; i < 4; i++) cpa16(Aoff[s] + dsta[i], ap[i] + kb + seg, 16); \
        _Pragma("unroll")                                                     \
        for (int i = 0; i < 2; i++) cpa16(Boff[s] + dstb[i], bp[i] + kb + seg, 16); \
        asm volatile("cp.async.commit_group;");                               \
    } while (0)

    const int mbase = (warp & 1) * 64;
    const int nbase = (warp >> 1) * 16;
    const int li  = lane & 7, grp = lane >> 3;
    const int ar  = (grp & 1) * 8 + li,  ak = (grp >> 1) * 16;
    const int br  = (grp >> 1) * 8 + li, bk = (grp & 1) * 16;
    const int g = lane >> 2, t = lane & 3;

    float acc[4][2][4] = {};

    DISSUE(0, 0);
#pragma unroll 1
    for (int c = 0; c < 8; c++) {
        if (c < 7) {
            DISSUE(c + 1, (c + 1) & 1);
            asm volatile("cp.async.wait_group 1;");
        } else {
            asm volatile("cp.async.wait_group 0;");
        }
        __syncthreads();
        const uint32_t Ab = Aoff[c & 1], Bb = Boff[c & 1];
#pragma unroll
        for (int kk = 0; kk < 4; kk++) {
            const int kb2 = kk * 32;
            uint32_t a[4][4], b[2][2];
#pragma unroll
            for (int mf = 0; mf < 4; mf++) {
                uint32_t o = (uint32_t)((mbase + mf * 16 + ar) * 128 + kb2 + ak);
                ldm4(a[mf], Ab + sw(o));
            }
            {
                uint32_t o = (uint32_t)((nbase + br) * 128 + kb2 + bk);
                uint32_t r[4]; ldm4(r, Bb + sw(o));
                b[0][0] = r[0]; b[0][1] = r[1];
                b[1][0] = r[2]; b[1][1] = r[3];
            }
#pragma unroll
            for (int mf = 0; mf < 4; mf++)
#pragma unroll
                for (int nf = 0; nf < 2; nf++)
                    mma_f16(acc[mf][nf], a[mf], b[nf]);
        }
        __syncthreads();
    }
#undef DISSUE

    // fused gen tail: stage W_gen slice loads
    const uint32_t Bg = base + A_T;
#pragma unroll
    for (int i = 0; i < 3; i++) {
        const int r = r0 + i * 32;
        if (r < MELS_)
            cpa16(Bg + sw((uint32_t)(r * 128 + seg)),
                  (const char*)g_wgenT + (long)r * 1024 + bx * 128 + seg, 16);
    }
    asm volatile("cp.async.commit_group;");

    // epilogue: bias + relu + fp16 -> g_dect and smem stage
#pragma unroll
    for (int mf = 0; mf < 4; mf++) {
        const int rl = mbase + mf * 16 + g;
        const long r0g = m0 + rl;
#pragma unroll
        for (int nf = 0; nf < 2; nf++) {
            const int cl = nbase + nf * 8 + t * 2;
            const int c = n0 + cl;
            const float b0 = bias[c], b1 = bias[c + 1];
            float v0 = acc[mf][nf][0] + b0, v1 = acc[mf][nf][1] + b1;
            float v2 = acc[mf][nf][2] + b0, v3 = acc[mf][nf][3] + b1;
            __half2 h0 = __floats2half2_rn(v0 > 0.f ? v0 : 0.f, v1 > 0.f ? v1 : 0.f);
            __half2 h1 = __floats2half2_rn(v2 > 0.f ? v2 : 0.f, v3 > 0.f ? v3 : 0.f);
            *(__half2*)(g_dect + r0g * D_ + c)       = h0;
            *(__half2*)(g_dect + (r0g + 8) * D_ + c) = h1;
            *(__half2*)(p_al + sw((uint32_t)(rl * 128 + cl * 2)))       = h0;
            *(__half2*)(p_al + sw((uint32_t)((rl + 8) * 128 + cl * 2))) = h1;
        }
    }
    asm volatile("cp.async.wait_group 0;");
    __syncthreads();

    // small gemm: 128 tok x 80 n x 64 k
    const int mb2 = (warp & 3) * 32, nb2 = (warp >> 2) * 40;
    float acc2[2][5][4] = {};
#pragma unroll
    for (int kk = 0; kk < 4; kk++) {
        const int kb2 = kk * 32;
        uint32_t a2[2][4], b2[5][2];
#pragma unroll
        for (int mf = 0; mf < 2; mf++)
            ldm4(a2[mf], base + sw((uint32_t)((mb2 + mf * 16 + ar) * 128 + kb2 + ak)));
#pragma unroll
        for (int nfp = 0; nfp < 2; nfp++) {
            uint32_t r[4];
            ldm4(r, Bg + sw((uint32_t)((nb2 + nfp * 16 + br) * 128 + kb2 + bk)));
            b2[nfp * 2][0] = r[0]; b2[nfp * 2][1] = r[1];
            b2[nfp * 2 + 1][0] = r[2]; b2[nfp * 2 + 1][1] = r[3];
        }
        ldm2(b2[4], Bg + sw((uint32_t)((nb2 + 32 + li) * 128 + kb2 + (grp & 1) * 16)));
#pragma unroll
        for (int mf = 0; mf < 2; mf++)
#pragma unroll
            for (int nf = 0; nf < 5; nf++)
                mma_f16(acc2[mf][nf], a2[mf], b2[nf]);
    }

#pragma unroll
    for (int mf = 0; mf < 2; mf++) {
        const int tok = m0 + mb2 + mf * 16 + g;
#pragma unroll
        for (int nf = 0; nf < 5; nf++) {
            const int n = nb2 + nf * 8 + t * 2;
            float* p = g_melP + ((long)bx * MELS_ + n) * M_ENC + tok;
            p[0]           = acc2[mf][nf][0];
            p[M_ENC]       = acc2[mf][nf][1];
            p[8]           = acc2[mf][nf][2];
            p[M_ENC + 8]   = acc2[mf][nf][3];
        }
    }
}

// ---------------------------------------------------------------------------
__global__ void __launch_bounds__(256, 2) mega_kernel(
    const int* __restrict__ src, const int* __restrict__ dur,
    const float* __restrict__ emb, const float* __restrict__ pos,
    const float* __restrict__ W_enc, const float* __restrict__ b_enc,
    const float* __restrict__ W_dur, const float* __restrict__ b_dur,
    const float* __restrict__ W_dec, const float* __restrict__ b_dec,
    const float* __restrict__ W_gen, const float* __restrict__ b_gen,
    float* __restrict__ mel, float* __restrict__ durp)
{
    extern __shared__ char dsm[];
    __shared__ float sbuf[32 * 33];
    __shared__ int s_tkt;
    const int cta = blockIdx.x;
    const int tid = threadIdx.x;
    const int bx = cta & 7, by = cta >> 3;

    // ---------------- prep stream ----------------
    t_unit(W_enc, g_wencT, cta, sbuf);
    signal(&fWe[(cta & 15) >> 1]);

    // prep_x: rows 16*cta .. +15 (exactly row-block `by`)
#pragma unroll 1
    for (int i = 0; i < 8; i++) {
        const long idx = ((long)cta * 8 + i) * 256 + tid;
        const int  m   = (int)(idx >> 7);
        const int  d4  = (int)(idx & 127) * 4;
        float4 e = *(const float4*)(emb + (long)src[m] * D_ + d4);
        float4 p = *(const float4*)(pos + (long)(m & (L_ - 1)) * D_ + d4);
        __half2 h0 = __floats2half2_rn(e.x + p.x, e.y + p.y);
        __half2 h1 = __floats2half2_rn(e.z + p.z, e.w + p.w);
        uint2 u = make_uint2(*(uint32_t*)&h0, *(uint32_t*)&h1);
        *(uint2*)(g_x + idx * 4) = u;
    }
    signal(&fX[by]);

    t_unit(W_dec, g_wdecT, cta, sbuf);
    signal(&fWd[(cta & 15) >> 1]);

    if (cta < 48) {
        // W_gen [D][MELS] -> g_wgenT [MELS][D]
        const int c0 = (cta % 3) * 32, r0 = (cta / 3) * 32;
        const int tx = tid & 31, ty = tid >> 5;
        float (*tile)[33] = (float(*)[33])sbuf;
#pragma unroll
        for (int i = 0; i < 4; i++) {
            int r = r0 + ty + i * 8, c = c0 + tx;
            if (c < MELS_) tile[ty + i * 8][tx] = W_gen[r * MELS_ + c];
        }
        __syncthreads();
#pragma unroll
        for (int i = 0; i < 4; i++) {
            int c = c0 + ty + i * 8, r = r0 + tx;
            if (c < MELS_)
                g_wgenT[(long)c * D_ + r] = __float2half_rn(tile[tx][ty + i * 8]);
        }
        signal(&fWg);
    } else if (cta < 64) {
        const int b = cta - 48;
        int* csum = (int*)sbuf;
        csum[tid] = dur[b * L_ + tid];
        __syncthreads();
        for (int off = 1; off < L_; off <<= 1) {
            int x = (tid >= off) ? csum[tid - off] : 0;
            __syncthreads();
            csum[tid] += x;
            __syncthreads();
        }
        g_csum[b * L_ + tid] = csum[tid];
        signal(&fS[b]);
    } else if (cta == 64) {
        float* rd = sbuf;
        for (int k = tid; k < D_; k += 256) {
            float v = b_dec[k]; rd[k] = v > 0.f ? v : 0.f;
        }
        __syncthreads();
        if (tid < MELS_) {
            float s = b_gen[tid];
            for (int k = 0; k < D_; k++) s += rd[k] * W_gen[k * MELS_ + tid];
            g_cmel[tid] = s;
        }
        signal(&fC);
    }

    // ---------------- enc ----------------
    waitf(&fWe[bx], 32);
    waitf(&fX[by], 8);
    dev_hgemm(g_x, g_wencT, b_enc, g_enc, bx, by, dsm);
    signal(&fE[by]);

    // ---------------- dec + fused gen ----------------
    waitf(&fE[by], 8);
    waitf(&fWd[bx], 32);
    waitf(&fWg, 48);
    dev_decgen(b_dec, bx, by, dsm);

    // ticket: 8th finisher of this row-block reduces the partials
    __threadfence();
    __syncthreads();
    if (tid == 0) s_tkt = atomicAdd(&fRB[by], 1);
    __syncthreads();
    if (s_tkt == 7) {
        __threadfence();
        const int m0 = by * 128;
#pragma unroll 1
        for (int idx = tid; idx < 128 * MELS_; idx += 256) {
            const int tok = m0 + (idx & 127);
            const int n   = idx >> 7;
            float s = b_gen[n];
#pragma unroll
            for (int x = 0; x < 8; x++)
                s += g_melP[((long)x * MELS_ + n) * M_ENC + tok];
            g_melT[(long)n * M_ENC + tok] = s;
        }
        signal(&fR[by]);
    }

    // ---------------- dur / expand ----------------
    if (cta < 64) {
        waitf(&fE[cta >> 1], 8);
        const int warp = tid >> 5, lane = tid & 31;
#pragma unroll 1
        for (int i = 0; i < 8; i++) {
            const int m = cta * 64 + warp * 8 + i;
            float s = 0.f;
            for (int k = lane; k < D_; k += 32)
                s += __half2float(g_enc[(long)m * D_ + k]) * W_dur[k];
#pragma unroll
            for (int o = 16; o; o >>= 1) s += __shfl_xor_sync(0xffffffffu, s, o);
            if (lane == 0) durp[m] = s + b_dur[0];
        }
    } else {
        const int u  = cta - 64;
        const int b  = u & (B_ - 1);
        const int t0 = (u >> 4) * 256;
        waitf(&fS[b], 1);
        waitf(&fC, 1);
        waitf(&fR[2 * b], 1);
        waitf(&fR[2 * b + 1], 1);

        int* csum = (int*)sbuf;
        csum[tid] = g_csum[b * L_ + tid];
        __syncthreads();

        const int t = t0 + tid;
        int lo = 0, hi = L_;
        while (lo < hi) {
            int mid = (lo + hi) >> 1;
            if (csum[mid] > t) hi = mid; else lo = mid + 1;
        }
        float* out = mel + (long)b * MELS_ * T_ + t;
        if (lo < L_) {
            const int tok = b * L_ + lo;
            const float* q = g_melT + tok;
#pragma unroll 8
            for (int n = 0; n < MELS_; n++)
                out[(long)n * T_] = __ldg(q + (long)n * M_ENC);
        } else {
#pragma unroll 4
            for (int n = 0; n < MELS_; n++)
                out[(long)n * T_] = g_cmel[n];
        }
    }

    // ---------------- final reset (last arrival) ----------------
    __threadfence();
    __syncthreads();
    if (tid == 0) {
        unsigned v = atomicAdd(&g_bar, 1u);
        if (v == (unsigned)NCTA - 1u) {
            fWg = 0; fC = 0;
            for (int i = 0; i < 8; i++) { fWe[i] = 0; fWd[i] = 0; }
            for (int i = 0; i < 32; i++) { fX[i] = 0; fE[i] = 0; fRB[i] = 0; fR[i] = 0; }
            for (int i = 0; i < 16; i++) fS[i] = 0;
            atomicExch(&g_bar, 0u);
        }
    }
}

// ---------------------------------------------------------------------------
extern "C" void kernel_launch(void* const* d_in, const int* in_sizes, int n_in,
                              void* d_out, int out_size)
{
    const int* src = (const int*)d_in[0];
    const int* dur = (const int*)d_in[1];
    int p = 2;
    if (p < n_in && in_sizes[2] <= 4) p = 3;  // skip scalar T if materialized
    const float* emb   = (const float*)d_in[p + 0];
    const float* pos   = (const float*)d_in[p + 1];
    const float* W_enc = (const float*)d_in[p + 2];
    const float* b_enc = (const float*)d_in[p + 3];
    const float* W_dur = (const float*)d_in[p + 4];
    const float* b_dur = (const float*)d_in[p + 5];
    const float* W_dec = (const float*)d_in[p + 6];
    const float* b_dec = (const float*)d_in[p + 7];
    const float* W_gen = (const float*)d_in[p + 8];
    const float* b_gen = (const float*)d_in[p + 9];

    float* mel  = (float*)d_out;                         // [B, MELS, T]
    float* durp = (float*)d_out + (long)B_ * MELS_ * T_; // [B, L]

    static bool attr_done = false;
    if (!attr_done) {
        cudaFuncSetAttribute(mega_kernel, cudaFuncAttributeMaxDynamicSharedMemorySize,
                             SMEM_DYN);
        attr_done = true;
    }

    mega_kernel<<<NCTA, 256, SMEM_DYN>>>(src, dur, emb, pos, W_enc, b_enc,
                                         W_dur, b_dur, W_dec, b_dec, W_gen, b_gen,
                                         mel, durp);
}

// round 15
// speedup vs baseline: 1.0255x; 1.0255x over previous
#include <cuda_runtime.h>
#include <cuda_fp16.h>
#include <cstdint>

#define B_    16
#define L_    256
#define D_    512
#define MELS_ 80
#define T_    3072
#define M_ENC (B_ * L_)   // 4096
#define NCTA  256

// Scratch (__device__ globals; no allocation allowed)
__device__ __half g_x    [M_ENC * D_];
__device__ __half g_enc  [M_ENC * D_];
__device__ __half g_dect [M_ENC * D_];
__device__ int    g_csum [B_ * L_];
__device__ float  g_melP [8 * MELS_ * M_ENC];  // per-bx gen partials [bx][n][tok]
__device__ float  g_cmel [MELS_];              // mel column for invalid frames (with bias)
__device__ __half g_wencT[D_ * D_];
__device__ __half g_wdecT[D_ * D_];
__device__ __half g_wgenT[MELS_ * D_];         // [n][k] fp16, 1KB rows

__device__ unsigned g_bar;
__device__ int fWe[8], fWd[8], fWg, fC;
__device__ int fE2[256];                       // per enc tile (by*8+bx)
__device__ int fX[32], fRB[32], fS[16];

// ---------------------------------------------------------------------------
__device__ __forceinline__ uint32_t smem_u32(const void* p) {
    return (uint32_t)__cvta_generic_to_shared(p);
}
__device__ __forceinline__ void cpa16(uint32_t dst, const void* src, int srcsize) {
    asm volatile("cp.async.cg.shared.global [%0], [%1], 16, %2;"
                 :: "r"(dst), "l"(src), "r"(srcsize));
}
__device__ __forceinline__ uint32_t sw(uint32_t o) { return o ^ ((o >> 3) & 0x70); }

__device__ __forceinline__ void ldm4(uint32_t* r, uint32_t addr) {
    asm volatile("ldmatrix.sync.aligned.m8n8.x4.shared.b16 {%0,%1,%2,%3}, [%4];"
                 : "=r"(r[0]), "=r"(r[1]), "=r"(r[2]), "=r"(r[3]) : "r"(addr));
}
__device__ __forceinline__ void ldm2(uint32_t* r, uint32_t addr) {
    asm volatile("ldmatrix.sync.aligned.m8n8.x2.shared.b16 {%0,%1}, [%2];"
                 : "=r"(r[0]), "=r"(r[1]) : "r"(addr));
}
__device__ __forceinline__ void mma_f16(float* d, const uint32_t* a, const uint32_t* b) {
    asm volatile(
        "mma.sync.aligned.m16n8k16.row.col.f32.f16.f16.f32 "
        "{%0,%1,%2,%3},{%4,%5,%6,%7},{%8,%9},{%0,%1,%2,%3};"
        : "+f"(d[0]), "+f"(d[1]), "+f"(d[2]), "+f"(d[3])
        : "r"(a[0]), "r"(a[1]), "r"(a[2]), "r"(a[3]), "r"(b[0]), "r"(b[1]));
}

__device__ __forceinline__ void signal(int* f) {
    __threadfence();
    __syncthreads();
    if (threadIdx.x == 0) atomicAdd(f, 1);
}
__device__ __forceinline__ void waitf(int* f, int tgt) {
    if (threadIdx.x == 0) {
        while (*(volatile int*)f < tgt) __nanosleep(32);
        __threadfence();
    }
    __syncthreads();
}

// ---------------------------------------------------------------------------
// 32x32 transpose tile of a 512x512 fp32 weight -> fp16 [N][K]
__device__ void t_unit(const float* __restrict__ srcw, __half* __restrict__ dst,
                       int id, float* sbuf)
{
    const int tid = threadIdx.x;
    const int c0 = (id & 15) * 32, r0 = (id >> 4) * 32;
    const int tx = tid & 31, ty = tid >> 5;
    float (*tile)[33] = (float(*)[33])sbuf;
#pragma unroll
    for (int i = 0; i < 4; i++)
        tile[ty + i * 8][tx] = srcw[(r0 + ty + i * 8) * D_ + c0 + tx];
    __syncthreads();
#pragma unroll
    for (int i = 0; i < 4; i++)
        dst[(long)(c0 + ty + i * 8) * D_ + r0 + tx] =
            __float2half_rn(tile[tx][ty + i * 8]);
}

// ---------------------------------------------------------------------------
// enc GEMM tile 128m x 64n: out = fp16(relu(A @ Bt^T + bias))
// ---------------------------------------------------------------------------
#define A_T 16384
#define B_T 8192
#define STG (A_T + B_T)                 // 24576
#define SMEM_DYN (2 * STG + 1024)       // 50176

__device__ void dev_hgemm(const __half* __restrict__ A, const __half* __restrict__ Bt,
                          const float* __restrict__ bias, __half* __restrict__ out,
                          int bx, int by, char* dsm)
{
    const int tid  = threadIdx.x;
    const int warp = tid >> 5, lane = tid & 31;
    const int m0   = by * 128, n0 = bx * 64;

    const uint32_t base = (smem_u32(dsm) + 1023) & ~1023u;
    const uint32_t Aoff[2] = { base, base + STG };
    const uint32_t Boff[2] = { base + A_T, base + STG + A_T };

    const int r0  = tid >> 3;
    const int seg = (tid & 7) * 16;
    const char* ap[4];
    const char* bp[2];
    uint32_t dsta[4], dstb[2];
#pragma unroll
    for (int i = 0; i < 4; i++) {
        const int r = r0 + i * 32;
        ap[i]   = (const char*)A + (long)(m0 + r) * D_ * 2;
        dsta[i] = sw((uint32_t)(r * 128 + seg));
    }
#pragma unroll
    for (int i = 0; i < 2; i++) {
        const int r = r0 + i * 32;
        bp[i]   = (const char*)Bt + (long)(n0 + r) * D_ * 2;
        dstb[i] = sw((uint32_t)(r * 128 + seg));
    }

#define HISSUE(c, s) do {                                                     \
        const int kb = (c) * 128;                                             \
        _Pragma("unroll")                                                     \
        for (int i = 0; i < 4; i++) cpa16(Aoff[s] + dsta[i], ap[i] + kb + seg, 16); \
        _Pragma("unroll")                                                     \
        for (int i = 0; i < 2; i++) cpa16(Boff[s] + dstb[i], bp[i] + kb + seg, 16); \
        asm volatile("cp.async.commit_group;");                               \
    } while (0)

    const int mbase = (warp & 1) * 64;
    const int nbase = (warp >> 1) * 16;
    const int li  = lane & 7, grp = lane >> 3;
    const int ar  = (grp & 1) * 8 + li,  ak = (grp >> 1) * 16;
    const int br  = (grp >> 1) * 8 + li, bk = (grp & 1) * 16;
    const int g = lane >> 2, t = lane & 3;

    float acc[4][2][4] = {};

    HISSUE(0, 0);
#pragma unroll 1
    for (int c = 0; c < 8; c++) {
        if (c < 7) {
            HISSUE(c + 1, (c + 1) & 1);
            asm volatile("cp.async.wait_group 1;");
        } else {
            asm volatile("cp.async.wait_group 0;");
        }
        __syncthreads();
        const uint32_t Ab = Aoff[c & 1], Bb = Boff[c & 1];
#pragma unroll
        for (int kk = 0; kk < 4; kk++) {
            const int kb2 = kk * 32;
            uint32_t a[4][4], b[2][2];
#pragma unroll
            for (int mf = 0; mf < 4; mf++) {
                uint32_t o = (uint32_t)((mbase + mf * 16 + ar) * 128 + kb2 + ak);
                ldm4(a[mf], Ab + sw(o));
            }
            {
                uint32_t o = (uint32_t)((nbase + br) * 128 + kb2 + bk);
                uint32_t r[4]; ldm4(r, Bb + sw(o));
                b[0][0] = r[0]; b[0][1] = r[1];
                b[1][0] = r[2]; b[1][1] = r[3];
            }
#pragma unroll
            for (int mf = 0; mf < 4; mf++)
#pragma unroll
                for (int nf = 0; nf < 2; nf++)
                    mma_f16(acc[mf][nf], a[mf], b[nf]);
        }
        __syncthreads();
    }

#pragma unroll
    for (int mf = 0; mf < 4; mf++) {
        const long r0g = m0 + mbase + mf * 16 + g;
#pragma unroll
        for (int nf = 0; nf < 2; nf++) {
            const int c = n0 + nbase + nf * 8 + t * 2;
            const float b0 = bias[c], b1 = bias[c + 1];
            float v0 = acc[mf][nf][0] + b0, v1 = acc[mf][nf][1] + b1;
            float v2 = acc[mf][nf][2] + b0, v3 = acc[mf][nf][3] + b1;
            __half2 h0 = __floats2half2_rn(v0 > 0.f ? v0 : 0.f, v1 > 0.f ? v1 : 0.f);
            __half2 h1 = __floats2half2_rn(v2 > 0.f ? v2 : 0.f, v3 > 0.f ? v3 : 0.f);
            *(__half2*)(out + r0g * D_ + c)       = h0;
            *(__half2*)(out + (r0g + 8) * D_ + c) = h1;
        }
    }
#undef HISSUE
}

// ---------------------------------------------------------------------------
// dec GEMM tile + fused gen partial; per-K-chunk waits on enc tile flags
// ---------------------------------------------------------------------------
__device__ void dev_decgen(const float* __restrict__ bias, int bx, int by, char* dsm)
{
    const int tid  = threadIdx.x;
    const int warp = tid >> 5, lane = tid & 31;
    const int m0   = by * 128, n0 = bx * 64;
    int* fEr = &fE2[by * 8];

    char* p_al = (char*)(((uintptr_t)dsm + 1023) & ~(uintptr_t)1023);
    const uint32_t base = smem_u32(p_al);
    const uint32_t Aoff[2] = { base, base + STG };
    const uint32_t Boff[2] = { base + A_T, base + STG + A_T };

    const int r0  = tid >> 3;
    const int seg = (tid & 7) * 16;
    const char* ap[4];
    const char* bp[2];
    uint32_t dsta[4], dstb[2];
#pragma unroll
    for (int i = 0; i < 4; i++) {
        const int r = r0 + i * 32;
        ap[i]   = (const char*)g_enc + (long)(m0 + r) * D_ * 2;
        dsta[i] = sw((uint32_t)(r * 128 + seg));
    }
#pragma unroll
    for (int i = 0; i < 2; i++) {
        const int r = r0 + i * 32;
        bp[i]   = (const char*)g_wdecT + (long)(n0 + r) * D_ * 2;
        dstb[i] = sw((uint32_t)(r * 128 + seg));
    }

#define DISSUE(c, s) do {                                                     \
        const int kb = (c) * 128;                                             \
        _Pragma("unroll")                                                     \
        for (int i = 0; i < 4; i++) cpa16(Aoff[s] + dsta[i], ap[i] + kb + seg, 16); \
        _Pragma("unroll")                                                     \
        for (int i = 0; i < 2; i++) cpa16(Boff[s] + dstb[i], bp[i] + kb + seg, 16); \
        asm volatile("cp.async.commit_group;");                               \
    } while (0)

    const int mbase = (warp & 1) * 64;
    const int nbase = (warp >> 1) * 16;
    const int li  = lane & 7, grp = lane >> 3;
    const int ar  = (grp & 1) * 8 + li,  ak = (grp >> 1) * 16;
    const int br  = (grp >> 1) * 8 + li, bk = (grp & 1) * 16;
    const int g = lane >> 2, t = lane & 3;

    float acc[4][2][4] = {};

    waitf(&fEr[0], 1);
    DISSUE(0, 0);
#pragma unroll 1
    for (int c = 0; c < 8; c++) {
        if (c < 7) {
            waitf(&fEr[c + 1], 1);
            DISSUE(c + 1, (c + 1) & 1);
            asm volatile("cp.async.wait_group 1;");
        } else {
            asm volatile("cp.async.wait_group 0;");
        }
        __syncthreads();
        const uint32_t Ab = Aoff[c & 1], Bb = Boff[c & 1];
#pragma unroll
        for (int kk = 0; kk < 4; kk++) {
            const int kb2 = kk * 32;
            uint32_t a[4][4], b[2][2];
#pragma unroll
            for (int mf = 0; mf < 4; mf++) {
                uint32_t o = (uint32_t)((mbase + mf * 16 + ar) * 128 + kb2 + ak);
                ldm4(a[mf], Ab + sw(o));
            }
            {
                uint32_t o = (uint32_t)((nbase + br) * 128 + kb2 + bk);
                uint32_t r[4]; ldm4(r, Bb + sw(o));
                b[0][0] = r[0]; b[0][1] = r[1];
                b[1][0] = r[2]; b[1][1] = r[3];
            }
#pragma unroll
            for (int mf = 0; mf < 4; mf++)
#pragma unroll
                for (int nf = 0; nf < 2; nf++)
                    mma_f16(acc[mf][nf], a[mf], b[nf]);
        }
        __syncthreads();
    }
#undef DISSUE

    // fused gen tail: stage W_gen slice loads
    const uint32_t Bg = base + A_T;
#pragma unroll
    for (int i = 0; i < 3; i++) {
        const int r = r0 + i * 32;
        if (r < MELS_)
            cpa16(Bg + sw((uint32_t)(r * 128 + seg)),
                  (const char*)g_wgenT + (long)r * 1024 + bx * 128 + seg, 16);
    }
    asm volatile("cp.async.commit_group;");

    // epilogue: bias + relu + fp16 -> g_dect and smem stage
#pragma unroll
    for (int mf = 0; mf < 4; mf++) {
        const int rl = mbase + mf * 16 + g;
        const long r0g = m0 + rl;
#pragma unroll
        for (int nf = 0; nf < 2; nf++) {
            const int cl = nbase + nf * 8 + t * 2;
            const int c = n0 + cl;
            const float b0 = bias[c], b1 = bias[c + 1];
            float v0 = acc[mf][nf][0] + b0, v1 = acc[mf][nf][1] + b1;
            float v2 = acc[mf][nf][2] + b0, v3 = acc[mf][nf][3] + b1;
            __half2 h0 = __floats2half2_rn(v0 > 0.f ? v0 : 0.f, v1 > 0.f ? v1 : 0.f);
            __half2 h1 = __floats2half2_rn(v2 > 0.f ? v2 : 0.f, v3 > 0.f ? v3 : 0.f);
            *(__half2*)(g_dect + r0g * D_ + c)       = h0;
            *(__half2*)(g_dect + (r0g + 8) * D_ + c) = h1;
            *(__half2*)(p_al + sw((uint32_t)(rl * 128 + cl * 2)))       = h0;
            *(__half2*)(p_al + sw((uint32_t)((rl + 8) * 128 + cl * 2))) = h1;
        }
    }
    asm volatile("cp.async.wait_group 0;");
    __syncthreads();

    // small gemm: 128 tok x 80 n x 64 k
    const int mb2 = (warp & 3) * 32, nb2 = (warp >> 2) * 40;
    float acc2[2][5][4] = {};
#pragma unroll
    for (int kk = 0; kk < 4; kk++) {
        const int kb2 = kk * 32;
        uint32_t a2[2][4], b2[5][2];
#pragma unroll
        for (int mf = 0; mf < 2; mf++)
            ldm4(a2[mf], base + sw((uint32_t)((mb2 + mf * 16 + ar) * 128 + kb2 + ak)));
#pragma unroll
        for (int nfp = 0; nfp < 2; nfp++) {
            uint32_t r[4];
            ldm4(r, Bg + sw((uint32_t)((nb2 + nfp * 16 + br) * 128 + kb2 + bk)));
            b2[nfp * 2][0] = r[0]; b2[nfp * 2][1] = r[1];
            b2[nfp * 2 + 1][0] = r[2]; b2[nfp * 2 + 1][1] = r[3];
        }
        ldm2(b2[4], Bg + sw((uint32_t)((nb2 + 32 + li) * 128 + kb2 + (grp & 1) * 16)));
#pragma unroll
        for (int mf = 0; mf < 2; mf++)
#pragma unroll
            for (int nf = 0; nf < 5; nf++)
                mma_f16(acc2[mf][nf], a2[mf], b2[nf]);
    }

#pragma unroll
    for (int mf = 0; mf < 2; mf++) {
        const int tok = m0 + mb2 + mf * 16 + g;
#pragma unroll
        for (int nf = 0; nf < 5; nf++) {
            const int n = nb2 + nf * 8 + t * 2;
            float* p = g_melP + ((long)bx * MELS_ + n) * M_ENC + tok;
            p[0]           = acc2[mf][nf][0];
            p[M_ENC]       = acc2[mf][nf][1];
            p[8]           = acc2[mf][nf][2];
            p[M_ENC + 8]   = acc2[mf][nf][3];
        }
    }
}

// ---------------------------------------------------------------------------
__global__ void __launch_bounds__(256, 2) mega_kernel(
    const int* __restrict__ src, const int* __restrict__ dur,
    const float* __restrict__ emb, const float* __restrict__ pos,
    const float* __restrict__ W_enc, const float* __restrict__ b_enc,
    const float* __restrict__ W_dur, const float* __restrict__ b_dur,
    const float* __restrict__ W_dec, const float* __restrict__ b_dec,
    const float* __restrict__ W_gen, const float* __restrict__ b_gen,
    float* __restrict__ mel, float* __restrict__ durp)
{
    extern __shared__ char dsm[];
    __shared__ float sbuf[32 * 33];
    __shared__ float bsh[MELS_];
    const int cta = blockIdx.x;
    const int tid = threadIdx.x;
    const int bx = cta & 7, by = cta >> 3;

    // ---------------- prep stream (no waits before these signals) ----------
    t_unit(W_enc, g_wencT, cta, sbuf);
    signal(&fWe[(cta & 15) >> 1]);

#pragma unroll 1
    for (int i = 0; i < 8; i++) {
        const long idx = ((long)cta * 8 + i) * 256 + tid;
        const int  m   = (int)(idx >> 7);
        const int  d4  = (int)(idx & 127) * 4;
        float4 e = *(const float4*)(emb + (long)src[m] * D_ + d4);
        float4 p = *(const float4*)(pos + (long)(m & (L_ - 1)) * D_ + d4);
        __half2 h0 = __floats2half2_rn(e.x + p.x, e.y + p.y);
        __half2 h1 = __floats2half2_rn(e.z + p.z, e.w + p.w);
        uint2 u = make_uint2(*(uint32_t*)&h0, *(uint32_t*)&h1);
        *(uint2*)(g_x + idx * 4) = u;
    }
    signal(&fX[by]);

    t_unit(W_dec, g_wdecT, cta, sbuf);
    signal(&fWd[(cta & 15) >> 1]);

    if (cta < 48) {
        const int c0 = (cta % 3) * 32, r0 = (cta / 3) * 32;
        const int tx = tid & 31, ty = tid >> 5;
        float (*tile)[33] = (float(*)[33])sbuf;
#pragma unroll
        for (int i = 0; i < 4; i++) {
            int r = r0 + ty + i * 8, c = c0 + tx;
            if (c < MELS_) tile[ty + i * 8][tx] = W_gen[r * MELS_ + c];
        }
        __syncthreads();
#pragma unroll
        for (int i = 0; i < 4; i++) {
            int c = c0 + ty + i * 8, r = r0 + tx;
            if (c < MELS_)
                g_wgenT[(long)c * D_ + r] = __float2half_rn(tile[tx][ty + i * 8]);
        }
        signal(&fWg);
    } else if (cta < 64) {
        const int b = cta - 48;
        int* csum = (int*)sbuf;
        csum[tid] = dur[b * L_ + tid];
        __syncthreads();
        for (int off = 1; off < L_; off <<= 1) {
            int x = (tid >= off) ? csum[tid - off] : 0;
            __syncthreads();
            csum[tid] += x;
            __syncthreads();
        }
        g_csum[b * L_ + tid] = csum[tid];
        signal(&fS[b]);
    } else if (cta == 64) {
        float* rd = sbuf;
        for (int k = tid; k < D_; k += 256) {
            float v = b_dec[k]; rd[k] = v > 0.f ? v : 0.f;
        }
        __syncthreads();
        if (tid < MELS_) {
            float s = b_gen[tid];
            for (int k = 0; k < D_; k++) s += rd[k] * W_gen[k * MELS_ + tid];
            g_cmel[tid] = s;
        }
        signal(&fC);
    }

    // ---------------- enc ----------------
    waitf(&fWe[bx], 32);
    waitf(&fX[by], 8);
    dev_hgemm(g_x, g_wencT, b_enc, g_enc, bx, by, dsm);
    signal(&fE2[cta]);                 // cta == by*8+bx

    // ---------------- dec + fused gen (per-chunk enc waits inside) --------
    waitf(&fWd[bx], 32);
    waitf(&fWg, 48);
    dev_decgen(b_dec, bx, by, dsm);
    signal(&fRB[by]);

    // ---------------- dur / expand ----------------
    if (cta < 64) {
        // duration head: rows 64*cta .. +63 (enc row-block cta>>1)
        int* fEr = &fE2[(cta >> 1) * 8];
        for (int j = 0; j < 8; j++) waitf(&fEr[j], 1);
        const int warp = tid >> 5, lane = tid & 31;
#pragma unroll 1
        for (int i = 0; i < 8; i++) {
            const int m = cta * 64 + warp * 8 + i;
            float s = 0.f;
            for (int k = lane; k < D_; k += 32)
                s += __half2float(g_enc[(long)m * D_ + k]) * W_dur[k];
#pragma unroll
            for (int o = 16; o; o >>= 1) s += __shfl_xor_sync(0xffffffffu, s, o);
            if (lane == 0) durp[m] = s + b_dur[0];
        }
    } else {
        // expand: one 256-frame unit per CTA
        const int u  = cta - 64;
        const int b  = u & (B_ - 1);
        const int t0 = (u >> 4) * 256;
        waitf(&fS[b], 1);
        waitf(&fC, 1);

        int* csum = (int*)sbuf;
        csum[tid] = g_csum[b * L_ + tid];
        if (tid < MELS_) bsh[tid] = b_gen[tid];
        __syncthreads();
        const int total = csum[L_ - 1];

        if (t0 < total) {              // unit touches valid frames: need gen
            waitf(&fRB[2 * b], 8);
            waitf(&fRB[2 * b + 1], 8);
        }

        const int t = t0 + tid;
        int lo = 0, hi = L_;
        while (lo < hi) {
            int mid = (lo + hi) >> 1;
            if (csum[mid] > t) hi = mid; else lo = mid + 1;
        }
        float* out = mel + (long)b * MELS_ * T_ + t;
        if (lo < L_) {
            const int tok = b * L_ + lo;
            const float* q = g_melP + tok;
#pragma unroll 4
            for (int n = 0; n < MELS_; n++) {
                float s = bsh[n];
#pragma unroll
                for (int x = 0; x < 8; x++)
                    s += __ldg(q + ((long)x * MELS_ + n) * M_ENC);
                out[(long)n * T_] = s;
            }
        } else {
#pragma unroll 4
            for (int n = 0; n < MELS_; n++)
                out[(long)n * T_] = g_cmel[n];
        }
    }

    // ---------------- final reset (last arrival) ----------------
    __threadfence();
    __syncthreads();
    if (tid == 0) {
        unsigned v = atomicAdd(&g_bar, 1u);
        if (v == (unsigned)NCTA - 1u) {
            fWg = 0; fC = 0;
            for (int i = 0; i < 8; i++) { fWe[i] = 0; fWd[i] = 0; }
            for (int i = 0; i < 256; i++) fE2[i] = 0;
            for (int i = 0; i < 32; i++) fRB[i] = 0;
            for (int i = 0; i < 32; i++) fX[i] = 0;
            for (int i = 0; i < 16; i++) fS[i] = 0;
            atomicExch(&g_bar, 0u);
        }
    }
}

// ---------------------------------------------------------------------------
extern "C" void kernel_launch(void* const* d_in, const int* in_sizes, int n_in,
                              void* d_out, int out_size)
{
    const int* src = (const int*)d_in[0];
    const int* dur = (const int*)d_in[1];
    int p = 2;
    if (p < n_in && in_sizes[2] <= 4) p = 3;  // skip scalar T if materialized
    const float* emb   = (const float*)d_in[p + 0];
    const float* pos   = (const float*)d_in[p + 1];
    const float* W_enc = (const float*)d_in[p + 2];
    const float* b_enc = (const float*)d_in[p + 3];
    const float* W_dur = (const float*)d_in[p + 4];
    const float* b_dur = (const float*)d_in[p + 5];
    const float* W_dec = (const float*)d_in[p + 6];
    const float* b_dec = (const float*)d_in[p + 7];
    const float* W_gen = (const float*)d_in[p + 8];
    const float* b_gen = (const float*)d_in[p + 9];

    float* mel  = (float*)d_out;                         // [B, MELS, T]
    float* durp = (float*)d_out + (long)B_ * MELS_ * T_; // [B, L]

    static bool attr_done = false;
    if (!attr_done) {
        cudaFuncSetAttribute(mega_kernel, cudaFuncAttributeMaxDynamicSharedMemorySize,
                             SMEM_DYN);
        attr_done = true;
    }

    mega_kernel<<<NCTA, 256, SMEM_DYN>>>(src, dur, emb, pos, W_enc, b_enc,
                                         W_dur, b_dur, W_dec, b_dec, W_gen, b_gen,
                                         mel, durp);
}